// round 8
// baseline (speedup 1.0000x reference)
#include <cuda_runtime.h>
#include <cuda_bf16.h>
#include <cstdint>

// Problem constants
#define VOCAB  32000
#define EMBED  100
#define HID    128
#define BATCH  1024
#define SEQ    256

// -------- device scratch (no allocation allowed) --------
__device__ __align__(16) float g_P[VOCAB * HID];            // fused projections (16.4 MB)
__device__ __align__(16) __nv_bfloat16 g_Ehi[VOCAB * 128];  // emb split (padded K=128)
__device__ __align__(16) __nv_bfloat16 g_Elo[VOCAB * 128];
__device__ __align__(16) __nv_bfloat16 g_Whi[VOCAB * 128];  // W_fc split
__device__ __align__(16) __nv_bfloat16 g_Wlo[VOCAB * 128];
__device__ __align__(16) __nv_bfloat16 g_IHhi[128 * 128];   // W_ih split
__device__ __align__(16) __nv_bfloat16 g_IHlo[128 * 128];
__device__ __align__(16) __nv_bfloat16 g_Hhi[BATCH * 128];  // h_last split
__device__ __align__(16) __nv_bfloat16 g_Hlo[BATCH * 128];

// ============================================================================
// Pre-split conversion: fp32 [rows][Kv] -> hi/lo bf16 [rows][128] (zero-pad).
// ============================================================================
__global__ void __launch_bounds__(256) k_cvt(
    const float* __restrict__ src, int Kv,
    __nv_bfloat16* __restrict__ hi, __nv_bfloat16* __restrict__ lo)
{
    const int r    = blockIdx.x * 8 + (threadIdx.x >> 5);
    const int lane = threadIdx.x & 31;
    #pragma unroll
    for (int cp = lane; cp < 64; cp += 32) {
        const int c0 = 2 * cp;
        float a = (c0     < Kv) ? src[(long long)r * Kv + c0]     : 0.0f;
        float b = (c0 + 1 < Kv) ? src[(long long)r * Kv + c0 + 1] : 0.0f;
        __nv_bfloat16 ha = __float2bfloat16_rn(a), hb = __float2bfloat16_rn(b);
        __nv_bfloat16 la = __float2bfloat16_rn(a - __bfloat162float(ha));
        __nv_bfloat16 lb = __float2bfloat16_rn(b - __bfloat162float(hb));
        ((uint32_t*)hi)[r * 64 + cp] = (uint32_t)*(uint16_t*)&ha | ((uint32_t)*(uint16_t*)&hb << 16);
        ((uint32_t*)lo)[r * 64 + cp] = (uint32_t)*(uint16_t*)&la | ((uint32_t)*(uint16_t*)&lb << 16);
    }
}

// ============================================================================
// mma.sync bf16 GEMM. D = Ahi*Bhi + Ahi*Blo + Alo*Bhi, fp32 accum.
// Block tile 128M x 64N, K=128 single-shot. 8 warps = 4M x 2N of 32x32.
// smem 96KB -> 2 CTAs/SM. Epilogue staged through smem (A-tile region,
// 68-float row pad) then written as coalesced 256B rows.
// ============================================================================
__device__ __forceinline__ uint32_t smem_u32(const void* p) {
    uint32_t a;
    asm("{ .reg .u64 t; cvta.to.shared.u64 t, %1; cvt.u32.u64 %0, t; }" : "=r"(a) : "l"(p));
    return a;
}
__device__ __forceinline__ void ldmx4(uint32_t* r, uint32_t a) {
    asm volatile("ldmatrix.sync.aligned.m8n8.x4.shared.b16 {%0,%1,%2,%3}, [%4];"
                 : "=r"(r[0]), "=r"(r[1]), "=r"(r[2]), "=r"(r[3]) : "r"(a));
}
__device__ __forceinline__ void mma_bf16(float* c, const uint32_t* a,
                                         uint32_t b0, uint32_t b1) {
    asm volatile("mma.sync.aligned.m16n8k16.row.col.f32.bf16.bf16.f32 "
                 "{%0,%1,%2,%3}, {%4,%5,%6,%7}, {%8,%9}, {%0,%1,%2,%3};"
                 : "+f"(c[0]), "+f"(c[1]), "+f"(c[2]), "+f"(c[3])
                 : "r"(a[0]), "r"(a[1]), "r"(a[2]), "r"(a[3]), "r"(b0), "r"(b1));
}
__device__ __forceinline__ uint32_t tswz(int row, int u) {
    return (uint32_t)(row * 256 + ((u ^ (row & 7)) << 4));
}
#define A_TILE 32768
#define B_TILE 16384
#define GEMM_SMEM (2 * A_TILE + 2 * B_TILE)   // 98304
#define EPAD 68   // staging row pad (floats): 272B, 16B-aligned, bank-shift 4

__device__ __forceinline__ void load_tile(const __nv_bfloat16* __restrict__ g,
                                          char* s, int rows, int tid) {
    #pragma unroll 4
    for (int i = tid; i < rows * 16; i += 256) {
        int row = i >> 4, u = i & 15;
        *(uint4*)(s + tswz(row, u)) = *(const uint4*)(g + (long long)row * 128 + u * 8);
    }
}

__global__ void __launch_bounds__(256, 2) k_gemm(
    const __nv_bfloat16* __restrict__ Ahi_g, const __nv_bfloat16* __restrict__ Alo_g,
    const __nv_bfloat16* __restrict__ Bhi_g, const __nv_bfloat16* __restrict__ Blo_g,
    float* __restrict__ out, long long ldout,
    const float* __restrict__ bias1, const float* __restrict__ bias2)
{
    extern __shared__ __align__(16) char sm[];
    __shared__ float sbias[64];
    char* Ahi = sm;
    char* Alo = sm + A_TILE;
    char* Bhi = sm + 2 * A_TILE;
    char* Blo = sm + 2 * A_TILE + B_TILE;

    const int tid = threadIdx.x, w = tid >> 5, lane = tid & 31;
    const int wm = w >> 1, wn = w & 1;
    const int m0 = blockIdx.x * 128, n0 = blockIdx.y * 64;

    load_tile(Ahi_g + (long long)m0 * 128, Ahi, 128, tid);
    load_tile(Alo_g + (long long)m0 * 128, Alo, 128, tid);
    load_tile(Bhi_g + (long long)n0 * 128, Bhi, 64, tid);
    load_tile(Blo_g + (long long)n0 * 128, Blo, 64, tid);
    if (tid < 64) sbias[tid] = bias1[n0 + tid] + (bias2 ? bias2[n0 + tid] : 0.0f);
    __syncthreads();

    const int sw = lane & 7;
    const int arow = wm * 32 + (lane & 15);
    const int akh  = lane >> 4;
    const int brow = wn * 32 + (lane & 7) + 8 * (lane >> 4);
    const int bkh  = (lane >> 3) & 1;

    const uint32_t sA0h = smem_u32(Ahi) + arow * 256;
    const uint32_t sA0l = smem_u32(Alo) + arow * 256;
    const uint32_t sB0h = smem_u32(Bhi) + brow * 256;
    const uint32_t sB0l = smem_u32(Blo) + brow * 256;

    float acc[2][4][4];
    #pragma unroll
    for (int mt = 0; mt < 2; mt++)
        #pragma unroll
        for (int nt = 0; nt < 4; nt++)
            #pragma unroll
            for (int q = 0; q < 4; q++) acc[mt][nt][q] = 0.0f;

    #pragma unroll
    for (int ks = 0; ks < 8; ks++) {
        const uint32_t uA = (uint32_t)(((2 * ks + akh) ^ sw) << 4);
        const uint32_t uB = (uint32_t)(((2 * ks + bkh) ^ sw) << 4);
        uint32_t aHi[2][4], aLo[2][4];
        ldmx4(aHi[0], sA0h + uA);
        ldmx4(aHi[1], sA0h + 16 * 256 + uA);
        ldmx4(aLo[0], sA0l + uA);
        ldmx4(aLo[1], sA0l + 16 * 256 + uA);
        #pragma unroll
        for (int np = 0; np < 2; np++) {
            uint32_t bh[4], bl[4];
            ldmx4(bh, sB0h + np * 16 * 256 + uB);
            ldmx4(bl, sB0l + np * 16 * 256 + uB);
            #pragma unroll
            for (int mt = 0; mt < 2; mt++) {
                mma_bf16(acc[mt][2 * np],     aHi[mt], bh[0], bh[1]);
                mma_bf16(acc[mt][2 * np + 1], aHi[mt], bh[2], bh[3]);
                mma_bf16(acc[mt][2 * np],     aLo[mt], bh[0], bh[1]);
                mma_bf16(acc[mt][2 * np + 1], aLo[mt], bh[2], bh[3]);
                mma_bf16(acc[mt][2 * np],     aHi[mt], bl[0], bl[1]);
                mma_bf16(acc[mt][2 * np + 1], aHi[mt], bl[2], bl[3]);
            }
        }
    }

    // ---- staged epilogue: frags -> smem (A region) -> coalesced GMEM ----
    __syncthreads();                 // all warps done reading tiles
    float* stg = (float*)sm;         // [128][EPAD], 34816 B < 64 KB
    const int g = lane >> 2, tig = lane & 3;
    #pragma unroll
    for (int mt = 0; mt < 2; mt++) {
        const int r0 = wm * 32 + mt * 16 + g;
        #pragma unroll
        for (int nt = 0; nt < 4; nt++) {
            const int col = wn * 32 + nt * 8 + 2 * tig;
            *(float2*)(stg + r0 * EPAD + col)       = make_float2(acc[mt][nt][0], acc[mt][nt][1]);
            *(float2*)(stg + (r0 + 8) * EPAD + col) = make_float2(acc[mt][nt][2], acc[mt][nt][3]);
        }
    }
    __syncthreads();
    #pragma unroll 4
    for (int i = tid; i < 128 * 16; i += 256) {
        const int row = i >> 4, u = i & 15, col = u * 4;
        float4 v = *(const float4*)(stg + row * EPAD + col);
        v.x += sbias[col]; v.y += sbias[col + 1]; v.z += sbias[col + 2]; v.w += sbias[col + 3];
        *(float4*)(out + (long long)(m0 + row) * ldout + n0 + col) = v;
    }
}

// ============================================================================
// Kernel B: RNN scan, k-split. 256 blocks x 256 threads; thread = (j, kh):
// j = hidden idx, kh = k-half. wpk = 32 packed pairs (64 regs) -> 4 warps/SMSP
// at 2 CTAs/SM for latency overlap. Per step: half-K matvec for 4 rows,
// smem partial reduce, each thread tanh's 2 rows. 2 bars/step.
// ============================================================================
__device__ __forceinline__ unsigned long long ffma2(unsigned long long a,
                                                    unsigned long long b,
                                                    unsigned long long c) {
    unsigned long long d;
    asm("fma.rn.f32x2 %0, %1, %2, %3;" : "=l"(d) : "l"(a), "l"(b), "l"(c));
    return d;
}
__device__ __forceinline__ float2 unpack2(unsigned long long v) {
    float lo, hi;
    asm("mov.b64 {%0, %1}, %2;" : "=f"(lo), "=f"(hi) : "l"(v));
    return make_float2(lo, hi);
}
__device__ __forceinline__ float fast_tanh(float x) {
    float e = __expf(2.0f * x);
    return 1.0f - __fdividef(2.0f, e + 1.0f);
}

__global__ void __launch_bounds__(256, 2) k_rnn_scan(
    const int* __restrict__ x, const float* __restrict__ W_hh)
{
    __shared__ __align__(16) float hbuf[2][4][HID];
    __shared__ float spart[2][4][HID];
    const int tid = threadIdx.x;
    const int j  = tid & 127;
    const int kh = tid >> 7;
    const int b0 = blockIdx.x * 4;

    // W_hh[j][kh*64 .. kh*64+63] as 32 packed pairs
    unsigned long long wpk[32];
    const unsigned long long* Wr = (const unsigned long long*)W_hh + (long long)j * 64 + kh * 32;
    #pragma unroll
    for (int q = 0; q < 32; q++) wpk[q] = Wr[q];

    if (kh == 0) {
        #pragma unroll
        for (int r = 0; r < 4; r++) hbuf[0][r][j] = 0.0f;
    }
    __syncthreads();

    // this thread tanh's rows 2kh, 2kh+1 -> it gathers P for those rows
    int idx0 = x[(b0 + 2 * kh) * SEQ];
    int idx1 = x[(b0 + 2 * kh + 1) * SEQ];

    int cur = 0;
    for (int t = 0; t < SEQ; t++) {
        const int n0i = (t < SEQ - 1) ? x[(b0 + 2 * kh) * SEQ + t + 1]     : idx0;
        const int n1i = (t < SEQ - 1) ? x[(b0 + 2 * kh + 1) * SEQ + t + 1] : idx1;
        const float px0 = g_P[idx0 * HID + j];
        const float px1 = g_P[idx1 * HID + j];

        unsigned long long acc[4];
        #pragma unroll
        for (int r = 0; r < 4; r++) acc[r] = 0ULL;

        #pragma unroll
        for (int q = 0; q < 16; q++) {
            #pragma unroll
            for (int r = 0; r < 4; r++) {
                ulonglong2 hv = ((const ulonglong2*)hbuf[cur][r])[kh * 16 + q];  // broadcast
                acc[r] = ffma2(hv.x, wpk[2 * q],     acc[r]);
                acc[r] = ffma2(hv.y, wpk[2 * q + 1], acc[r]);
            }
        }
        #pragma unroll
        for (int r = 0; r < 4; r++) {
            float2 s = unpack2(acc[r]);
            spart[kh][r][j] = s.x + s.y;
        }
        __syncthreads();

        const int r0 = 2 * kh;
        const float v0 = spart[0][r0][j]     + spart[1][r0][j]     + px0;
        const float v1 = spart[0][r0 + 1][j] + spart[1][r0 + 1][j] + px1;
        const int nxt = cur ^ 1;
        hbuf[nxt][r0][j]     = fast_tanh(v0);
        hbuf[nxt][r0 + 1][j] = fast_tanh(v1);
        idx0 = n0i; idx1 = n1i; cur = nxt;
        __syncthreads();
    }

    // epilogue: split h -> hi/lo bf16 packed pairs (kh==0 threads, j<64)
    if (kh == 0 && j < 64) {
        #pragma unroll
        for (int r = 0; r < 4; r++) {
            float a = hbuf[cur][r][2 * j], b = hbuf[cur][r][2 * j + 1];
            __nv_bfloat16 ha = __float2bfloat16_rn(a), hb = __float2bfloat16_rn(b);
            __nv_bfloat16 la = __float2bfloat16_rn(a - __bfloat162float(ha));
            __nv_bfloat16 lb = __float2bfloat16_rn(b - __bfloat162float(hb));
            ((uint32_t*)g_Hhi)[(b0 + r) * 64 + j] =
                (uint32_t)*(uint16_t*)&ha | ((uint32_t)*(uint16_t*)&hb << 16);
            ((uint32_t*)g_Hlo)[(b0 + r) * 64 + j] =
                (uint32_t)*(uint16_t*)&la | ((uint32_t)*(uint16_t*)&lb << 16);
        }
    }
}

// ============================================================================
// launch
// ============================================================================
extern "C" void kernel_launch(void* const* d_in, const int* in_sizes, int n_in,
                              void* d_out, int out_size) {
    const int*   x    = (const int*)d_in[0];     // int32: JAX downcasts int64
    const float* emb  = (const float*)d_in[1];
    const float* W_ih = (const float*)d_in[2];
    const float* W_hh = (const float*)d_in[3];
    const float* b_ih = (const float*)d_in[4];
    const float* b_hh = (const float*)d_in[5];
    const float* W_fc = (const float*)d_in[6];
    const float* b_fc = (const float*)d_in[7];
    float*       out  = (float*)d_out;

    static float* P_p = nullptr;
    static __nv_bfloat16 *Ehi_p, *Elo_p, *Whi_p, *Wlo_p, *IHhi_p, *IHlo_p, *Hhi_p, *Hlo_p;
    if (!P_p) {
        cudaGetSymbolAddress((void**)&P_p,    g_P);
        cudaGetSymbolAddress((void**)&Ehi_p,  g_Ehi);
        cudaGetSymbolAddress((void**)&Elo_p,  g_Elo);
        cudaGetSymbolAddress((void**)&Whi_p,  g_Whi);
        cudaGetSymbolAddress((void**)&Wlo_p,  g_Wlo);
        cudaGetSymbolAddress((void**)&IHhi_p, g_IHhi);
        cudaGetSymbolAddress((void**)&IHlo_p, g_IHlo);
        cudaGetSymbolAddress((void**)&Hhi_p,  g_Hhi);
        cudaGetSymbolAddress((void**)&Hlo_p,  g_Hlo);
        cudaFuncSetAttribute(k_gemm, cudaFuncAttributeMaxDynamicSharedMemorySize, GEMM_SMEM);
    }

    // pre-split weights/embeddings to hi/lo bf16 (K padded to 128)
    k_cvt<<<VOCAB / 8, 256>>>(emb,  EMBED, Ehi_p,  Elo_p);
    k_cvt<<<HID / 8,   256>>>(W_ih, EMBED, IHhi_p, IHlo_p);
    k_cvt<<<VOCAB / 8, 256>>>(W_fc, HID,   Whi_p,  Wlo_p);

    // P[v][j] = emb[v]·W_ih[j] + (b_ih+b_hh)[j]
    k_gemm<<<dim3(VOCAB / 128, HID / 64), 256, GEMM_SMEM>>>(
        Ehi_p, Elo_p, IHhi_p, IHlo_p, P_p, HID, b_ih, b_hh);

    // recurrent scan (writes g_Hhi/g_Hlo)
    k_rnn_scan<<<BATCH / 4, 256>>>(x, W_hh);

    // out[b][v] = h[b]·W_fc[v] + b_fc[v]; x=batch so consecutive CTAs share W_fc tile in L2
    k_gemm<<<dim3(BATCH / 128, VOCAB / 64), 256, GEMM_SMEM>>>(
        Hhi_p, Hlo_p, Whi_p, Wlo_p, out, VOCAB, b_fc, nullptr);
}

// round 9
// speedup vs baseline: 1.0571x; 1.0571x over previous
#include <cuda_runtime.h>
#include <cuda_bf16.h>
#include <cstdint>

// Problem constants
#define VOCAB  32000
#define EMBED  100
#define HID    128
#define BATCH  1024
#define SEQ    256

// -------- device scratch (no allocation allowed) --------
__device__ __align__(16) float g_P[VOCAB * HID];            // fused projections (16.4 MB)
__device__ __align__(16) __nv_bfloat16 g_Ehi[VOCAB * 128];  // emb split (padded K=128)
__device__ __align__(16) __nv_bfloat16 g_Elo[VOCAB * 128];
__device__ __align__(16) __nv_bfloat16 g_Whi[VOCAB * 128];  // W_fc split
__device__ __align__(16) __nv_bfloat16 g_Wlo[VOCAB * 128];
__device__ __align__(16) __nv_bfloat16 g_IHhi[128 * 128];   // W_ih split
__device__ __align__(16) __nv_bfloat16 g_IHlo[128 * 128];
__device__ __align__(16) __nv_bfloat16 g_WHhi[128 * 128];   // W_hh split
__device__ __align__(16) __nv_bfloat16 g_WHlo[128 * 128];
__device__ __align__(16) __nv_bfloat16 g_Hhi[BATCH * 128];  // h_last split
__device__ __align__(16) __nv_bfloat16 g_Hlo[BATCH * 128];

// ============================================================================
// Pre-split conversion: fp32 [rows][Kv] -> hi/lo bf16 [rows][128] (zero-pad).
// ============================================================================
__global__ void __launch_bounds__(256) k_cvt(
    const float* __restrict__ src, int Kv,
    __nv_bfloat16* __restrict__ hi, __nv_bfloat16* __restrict__ lo)
{
    const int r    = blockIdx.x * 8 + (threadIdx.x >> 5);
    const int lane = threadIdx.x & 31;
    #pragma unroll
    for (int cp = lane; cp < 64; cp += 32) {
        const int c0 = 2 * cp;
        float a = (c0     < Kv) ? src[(long long)r * Kv + c0]     : 0.0f;
        float b = (c0 + 1 < Kv) ? src[(long long)r * Kv + c0 + 1] : 0.0f;
        __nv_bfloat16 ha = __float2bfloat16_rn(a), hb = __float2bfloat16_rn(b);
        __nv_bfloat16 la = __float2bfloat16_rn(a - __bfloat162float(ha));
        __nv_bfloat16 lb = __float2bfloat16_rn(b - __bfloat162float(hb));
        ((uint32_t*)hi)[r * 64 + cp] = (uint32_t)*(uint16_t*)&ha | ((uint32_t)*(uint16_t*)&hb << 16);
        ((uint32_t*)lo)[r * 64 + cp] = (uint32_t)*(uint16_t*)&la | ((uint32_t)*(uint16_t*)&lb << 16);
    }
}

// ============================================================================
// mma.sync helpers (validated in passing rounds)
// ============================================================================
__device__ __forceinline__ uint32_t smem_u32(const void* p) {
    uint32_t a;
    asm("{ .reg .u64 t; cvta.to.shared.u64 t, %1; cvt.u32.u64 %0, t; }" : "=r"(a) : "l"(p));
    return a;
}
__device__ __forceinline__ void ldmx4(uint32_t* r, uint32_t a) {
    asm volatile("ldmatrix.sync.aligned.m8n8.x4.shared.b16 {%0,%1,%2,%3}, [%4];"
                 : "=r"(r[0]), "=r"(r[1]), "=r"(r[2]), "=r"(r[3]) : "r"(a));
}
__device__ __forceinline__ void mma_bf16(float* c, const uint32_t* a,
                                         uint32_t b0, uint32_t b1) {
    asm volatile("mma.sync.aligned.m16n8k16.row.col.f32.bf16.bf16.f32 "
                 "{%0,%1,%2,%3}, {%4,%5,%6,%7}, {%8,%9}, {%0,%1,%2,%3};"
                 : "+f"(c[0]), "+f"(c[1]), "+f"(c[2]), "+f"(c[3])
                 : "r"(a[0]), "r"(a[1]), "r"(a[2]), "r"(a[3]), "r"(b0), "r"(b1));
}
__device__ __forceinline__ uint32_t tswz(int row, int u) {
    return (uint32_t)(row * 256 + ((u ^ (row & 7)) << 4));
}
__device__ __forceinline__ void load_tile(const __nv_bfloat16* __restrict__ g,
                                          char* s, int rows, int tid) {
    #pragma unroll 4
    for (int i = tid; i < rows * 16; i += 256) {
        int row = i >> 4, u = i & 15;
        *(uint4*)(s + tswz(row, u)) = *(const uint4*)(g + (long long)row * 128 + u * 8);
    }
}
__device__ __forceinline__ float fast_tanh(float x) {
    float e = __expf(2.0f * x);
    return 1.0f - __fdividef(2.0f, e + 1.0f);
}
__device__ __forceinline__ uint32_t pack_hi(float a, float b,
                                            uint32_t& lo_out) {
    __nv_bfloat16 ha = __float2bfloat16_rn(a), hb = __float2bfloat16_rn(b);
    __nv_bfloat16 la = __float2bfloat16_rn(a - __bfloat162float(ha));
    __nv_bfloat16 lb = __float2bfloat16_rn(b - __bfloat162float(hb));
    lo_out = (uint32_t)*(uint16_t*)&la | ((uint32_t)*(uint16_t*)&lb << 16);
    return (uint32_t)*(uint16_t*)&ha | ((uint32_t)*(uint16_t*)&hb << 16);
}

// ============================================================================
// GEMM: block tile 128M x 64N, K=128, 8 warps (4M x 2N of 32x32), occ 2.
// ============================================================================
#define A_TILE 32768
#define B_TILE 16384
#define GEMM_SMEM (2 * A_TILE + 2 * B_TILE)   // 98304
#define EPAD 68

__global__ void __launch_bounds__(256, 2) k_gemm(
    const __nv_bfloat16* __restrict__ Ahi_g, const __nv_bfloat16* __restrict__ Alo_g,
    const __nv_bfloat16* __restrict__ Bhi_g, const __nv_bfloat16* __restrict__ Blo_g,
    float* __restrict__ out, long long ldout,
    const float* __restrict__ bias1, const float* __restrict__ bias2)
{
    extern __shared__ __align__(16) char sm[];
    __shared__ float sbias[64];
    char* Ahi = sm;
    char* Alo = sm + A_TILE;
    char* Bhi = sm + 2 * A_TILE;
    char* Blo = sm + 2 * A_TILE + B_TILE;

    const int tid = threadIdx.x, w = tid >> 5, lane = tid & 31;
    const int wm = w >> 1, wn = w & 1;
    const int m0 = blockIdx.x * 128, n0 = blockIdx.y * 64;

    load_tile(Ahi_g + (long long)m0 * 128, Ahi, 128, tid);
    load_tile(Alo_g + (long long)m0 * 128, Alo, 128, tid);
    load_tile(Bhi_g + (long long)n0 * 128, Bhi, 64, tid);
    load_tile(Blo_g + (long long)n0 * 128, Blo, 64, tid);
    if (tid < 64) sbias[tid] = bias1[n0 + tid] + (bias2 ? bias2[n0 + tid] : 0.0f);
    __syncthreads();

    const int sw = lane & 7;
    const int arow = wm * 32 + (lane & 15);
    const int akh  = lane >> 4;
    const int brow = wn * 32 + (lane & 7) + 8 * (lane >> 4);
    const int bkh  = (lane >> 3) & 1;

    const uint32_t sA0h = smem_u32(Ahi) + arow * 256;
    const uint32_t sA0l = smem_u32(Alo) + arow * 256;
    const uint32_t sB0h = smem_u32(Bhi) + brow * 256;
    const uint32_t sB0l = smem_u32(Blo) + brow * 256;

    float acc[2][4][4];
    #pragma unroll
    for (int mt = 0; mt < 2; mt++)
        #pragma unroll
        for (int nt = 0; nt < 4; nt++)
            #pragma unroll
            for (int q = 0; q < 4; q++) acc[mt][nt][q] = 0.0f;

    #pragma unroll
    for (int ks = 0; ks < 8; ks++) {
        const uint32_t uA = (uint32_t)(((2 * ks + akh) ^ sw) << 4);
        const uint32_t uB = (uint32_t)(((2 * ks + bkh) ^ sw) << 4);
        uint32_t aHi[2][4], aLo[2][4];
        ldmx4(aHi[0], sA0h + uA);
        ldmx4(aHi[1], sA0h + 16 * 256 + uA);
        ldmx4(aLo[0], sA0l + uA);
        ldmx4(aLo[1], sA0l + 16 * 256 + uA);
        #pragma unroll
        for (int np = 0; np < 2; np++) {
            uint32_t bh[4], bl[4];
            ldmx4(bh, sB0h + np * 16 * 256 + uB);
            ldmx4(bl, sB0l + np * 16 * 256 + uB);
            #pragma unroll
            for (int mt = 0; mt < 2; mt++) {
                mma_bf16(acc[mt][2 * np],     aHi[mt], bh[0], bh[1]);
                mma_bf16(acc[mt][2 * np + 1], aHi[mt], bh[2], bh[3]);
                mma_bf16(acc[mt][2 * np],     aLo[mt], bh[0], bh[1]);
                mma_bf16(acc[mt][2 * np + 1], aLo[mt], bh[2], bh[3]);
                mma_bf16(acc[mt][2 * np],     aHi[mt], bl[0], bl[1]);
                mma_bf16(acc[mt][2 * np + 1], aHi[mt], bl[2], bl[3]);
            }
        }
    }

    __syncthreads();
    float* stg = (float*)sm;
    const int g = lane >> 2, tig = lane & 3;
    #pragma unroll
    for (int mt = 0; mt < 2; mt++) {
        const int r0 = wm * 32 + mt * 16 + g;
        #pragma unroll
        for (int nt = 0; nt < 4; nt++) {
            const int col = wn * 32 + nt * 8 + 2 * tig;
            *(float2*)(stg + r0 * EPAD + col)       = make_float2(acc[mt][nt][0], acc[mt][nt][1]);
            *(float2*)(stg + (r0 + 8) * EPAD + col) = make_float2(acc[mt][nt][2], acc[mt][nt][3]);
        }
    }
    __syncthreads();
    #pragma unroll 4
    for (int i = tid; i < 128 * 16; i += 256) {
        const int row = i >> 4, u = i & 15, col = u * 4;
        float4 v = *(const float4*)(stg + row * EPAD + col);
        v.x += sbias[col]; v.y += sbias[col + 1]; v.z += sbias[col + 2]; v.w += sbias[col + 3];
        *(float4*)(out + (long long)(m0 + row) * ldout + n0 + col) = v;
    }
}

// ============================================================================
// Kernel B: MMA-based RNN scan. 64 CTAs x 256 threads; CTA owns 16 batch rows.
// W_hh hi/lo resident in smem, B-fragments PRELOADED into registers (static
// across steps -> zero LDSM for B in the loop). h in double-buffered swizzled
// A-tiles (hi/lo). Per step/warp: 16 LDSM (A) + 48 HMMA (3 split terms, 3
// independent acc chains), P gathered from L2 at step top (hidden under MMA),
// tanh + re-split epilogue, ONE __syncthreads (ping-pong).
// Warp w computes output cols j in [16w, 16w+16).
// ============================================================================
#define SXP 260
#define SCAN_OFF_WH  0                    // W_hh hi (32KB) + lo (32KB)
#define SCAN_OFF_AT  65536                // A tiles: [buf][hilo] 4KB each
#define SCAN_OFF_SX  (65536 + 16384)      // x stage: 16 x SXP ints
#define SCAN_SMEM    (SCAN_OFF_SX + 16 * SXP * 4)

__global__ void __launch_bounds__(256, 1) k_rnn_mma(const int* __restrict__ x)
{
    extern __shared__ __align__(16) char sm[];
    char* WHhi = sm + SCAN_OFF_WH;
    char* WHlo = sm + SCAN_OFF_WH + 32768;
    char* AT   = sm + SCAN_OFF_AT;        // AT + buf*8192 + hilo*4096
    int*  sx   = (int*)(sm + SCAN_OFF_SX);

    const int tid = threadIdx.x, w = tid >> 5, lane = tid & 31;
    const int b0 = blockIdx.x * 16;

    // prologue: W_hh tiles, x stage, zero h buffer 0
    load_tile(g_WHhi, WHhi, 128, tid);
    load_tile(g_WHlo, WHlo, 128, tid);
    for (int i = tid; i < 16 * SEQ; i += 256) {
        int row = i >> 8, t = i & 255;
        sx[row * SXP + t] = x[(b0 + row) * SEQ + t];
    }
    for (int i = tid; i < 512; i += 256)
        ((uint4*)AT)[i] = make_uint4(0, 0, 0, 0);
    __syncthreads();

    // preload B fragments (W_hh) — static for all 256 steps
    const int sw = lane & 7;
    const int brow = w * 16 + (lane & 7) + 8 * (lane >> 4);
    const int bkh  = (lane >> 3) & 1;
    const uint32_t sBh = smem_u32(WHhi) + brow * 256;
    const uint32_t sBl = smem_u32(WHlo) + brow * 256;
    uint32_t bfh[8][4], bfl[8][4];
    #pragma unroll
    for (int ks = 0; ks < 8; ks++) {
        const uint32_t uB = (uint32_t)(((2 * ks + bkh) ^ sw) << 4);
        ldmx4(bfh[ks], sBh + uB);
        ldmx4(bfl[ks], sBl + uB);
    }

    // A-frag addressing (row within 16-row h tile)
    const int arow = lane & 15;
    const int akh  = lane >> 4;
    const uint32_t aBase[2][2] = {
        { smem_u32(AT) + arow * 256,        smem_u32(AT) + 4096 + arow * 256 },
        { smem_u32(AT) + 8192 + arow * 256, smem_u32(AT) + 12288 + arow * 256 } };

    // epilogue addressing: thread owns rows g, g+8; cols w*16 + nt*8 + 2*tig
    const int g = lane >> 2, tig = lane & 3;
    const int cb[2] = { w * 16 + 2 * tig, w * 16 + 8 + 2 * tig };
    // smem store offsets for packed col pair (nt unit = 2w+nt)
    uint32_t stoff[2][2];   // [rowhalf][nt]
    #pragma unroll
    for (int rh = 0; rh < 2; rh++) {
        const int row = g + rh * 8;
        #pragma unroll
        for (int nt = 0; nt < 2; nt++)
            stoff[rh][nt] = (uint32_t)(row * 256 + (((2 * w + nt) ^ (row & 7)) << 4) + 4 * tig);
    }

    int cur = 0;
    for (int t = 0; t < SEQ; t++) {
        // P gather (consumed post-MMA; L2 latency hides under the 48 HMMA)
        const int idx0 = sx[g * SXP + t];
        const int idx1 = sx[(g + 8) * SXP + t];
        float2 px[2][2];
        px[0][0] = *(const float2*)(g_P + idx0 * HID + cb[0]);
        px[0][1] = *(const float2*)(g_P + idx0 * HID + cb[1]);
        px[1][0] = *(const float2*)(g_P + idx1 * HID + cb[0]);
        px[1][1] = *(const float2*)(g_P + idx1 * HID + cb[1]);

        float accH[2][4], accM[2][4], accL[2][4];
        #pragma unroll
        for (int nt = 0; nt < 2; nt++)
            #pragma unroll
            for (int q = 0; q < 4; q++) { accH[nt][q] = 0.f; accM[nt][q] = 0.f; accL[nt][q] = 0.f; }

        const uint32_t aH = aBase[cur][0], aL = aBase[cur][1];
        #pragma unroll
        for (int ks = 0; ks < 8; ks++) {
            const uint32_t uA = (uint32_t)(((2 * ks + akh) ^ sw) << 4);
            uint32_t ahi[4], alo[4];
            ldmx4(ahi, aH + uA);
            ldmx4(alo, aL + uA);
            mma_bf16(accH[0], ahi, bfh[ks][0], bfh[ks][1]);
            mma_bf16(accH[1], ahi, bfh[ks][2], bfh[ks][3]);
            mma_bf16(accM[0], ahi, bfl[ks][0], bfl[ks][1]);
            mma_bf16(accM[1], ahi, bfl[ks][2], bfl[ks][3]);
            mma_bf16(accL[0], alo, bfh[ks][0], bfh[ks][1]);
            mma_bf16(accL[1], alo, bfh[ks][2], bfh[ks][3]);
        }

        // epilogue: v = mma + P; h = tanh(v); split -> next h buffer
        const int nxt = cur ^ 1;
        char* Dhi = AT + nxt * 8192;
        char* Dlo = AT + nxt * 8192 + 4096;
        #pragma unroll
        for (int rh = 0; rh < 2; rh++) {
            #pragma unroll
            for (int nt = 0; nt < 2; nt++) {
                const int q0 = 2 * rh;
                float v0 = accH[nt][q0]     + accM[nt][q0]     + accL[nt][q0]     + px[rh][nt].x;
                float v1 = accH[nt][q0 + 1] + accM[nt][q0 + 1] + accL[nt][q0 + 1] + px[rh][nt].y;
                float h0 = fast_tanh(v0), h1 = fast_tanh(v1);
                uint32_t plo, phi = pack_hi(h0, h1, plo);
                *(uint32_t*)(Dhi + stoff[rh][nt]) = phi;
                *(uint32_t*)(Dlo + stoff[rh][nt]) = plo;
            }
        }
        cur = nxt;
        __syncthreads();
    }

    // write final h (already split) to global
    char* Fhi = AT + cur * 8192;
    char* Flo = AT + cur * 8192 + 4096;
    for (int i = tid; i < 16 * 64; i += 256) {
        const int row = i >> 6, cp = i & 63;
        const uint32_t off = (uint32_t)(row * 256 + (((cp >> 2) ^ (row & 7)) << 4) + (cp & 3) * 4);
        ((uint32_t*)g_Hhi)[(b0 + row) * 64 + cp] = *(const uint32_t*)(Fhi + off);
        ((uint32_t*)g_Hlo)[(b0 + row) * 64 + cp] = *(const uint32_t*)(Flo + off);
    }
}

// ============================================================================
// launch
// ============================================================================
extern "C" void kernel_launch(void* const* d_in, const int* in_sizes, int n_in,
                              void* d_out, int out_size) {
    const int*   x    = (const int*)d_in[0];     // int32: JAX downcasts int64
    const float* emb  = (const float*)d_in[1];
    const float* W_ih = (const float*)d_in[2];
    const float* W_hh = (const float*)d_in[3];
    const float* b_ih = (const float*)d_in[4];
    const float* b_hh = (const float*)d_in[5];
    const float* W_fc = (const float*)d_in[6];
    const float* b_fc = (const float*)d_in[7];
    float*       out  = (float*)d_out;

    static float* P_p = nullptr;
    static __nv_bfloat16 *Ehi_p, *Elo_p, *Whi_p, *Wlo_p, *IHhi_p, *IHlo_p;
    static __nv_bfloat16 *WHhi_p, *WHlo_p, *Hhi_p, *Hlo_p;
    if (!P_p) {
        cudaGetSymbolAddress((void**)&P_p,    g_P);
        cudaGetSymbolAddress((void**)&Ehi_p,  g_Ehi);
        cudaGetSymbolAddress((void**)&Elo_p,  g_Elo);
        cudaGetSymbolAddress((void**)&Whi_p,  g_Whi);
        cudaGetSymbolAddress((void**)&Wlo_p,  g_Wlo);
        cudaGetSymbolAddress((void**)&IHhi_p, g_IHhi);
        cudaGetSymbolAddress((void**)&IHlo_p, g_IHlo);
        cudaGetSymbolAddress((void**)&WHhi_p, g_WHhi);
        cudaGetSymbolAddress((void**)&WHlo_p, g_WHlo);
        cudaGetSymbolAddress((void**)&Hhi_p,  g_Hhi);
        cudaGetSymbolAddress((void**)&Hlo_p,  g_Hlo);
        cudaFuncSetAttribute(k_gemm,    cudaFuncAttributeMaxDynamicSharedMemorySize, GEMM_SMEM);
        cudaFuncSetAttribute(k_rnn_mma, cudaFuncAttributeMaxDynamicSharedMemorySize, SCAN_SMEM);
    }

    // pre-split weights/embeddings to hi/lo bf16 (K padded to 128)
    k_cvt<<<VOCAB / 8, 256>>>(emb,  EMBED, Ehi_p,  Elo_p);
    k_cvt<<<HID / 8,   256>>>(W_ih, EMBED, IHhi_p, IHlo_p);
    k_cvt<<<HID / 8,   256>>>(W_hh, HID,   WHhi_p, WHlo_p);
    k_cvt<<<VOCAB / 8, 256>>>(W_fc, HID,   Whi_p,  Wlo_p);

    // P[v][j] = emb[v]·W_ih[j] + (b_ih+b_hh)[j]
    k_gemm<<<dim3(VOCAB / 128, HID / 64), 256, GEMM_SMEM>>>(
        Ehi_p, Elo_p, IHhi_p, IHlo_p, P_p, HID, b_ih, b_hh);

    // recurrent scan on tensor cores (writes g_Hhi/g_Hlo)
    k_rnn_mma<<<BATCH / 16, 256, SCAN_SMEM>>>(x);

    // out[b][v] = h[b]·W_fc[v] + b_fc[v]
    k_gemm<<<dim3(BATCH / 128, VOCAB / 64), 256, GEMM_SMEM>>>(
        Hhi_p, Hlo_p, Whi_p, Wlo_p, out, VOCAB, b_fc, nullptr);
}